// round 1
// baseline (speedup 1.0000x reference)
#include <cuda_runtime.h>
#include <math.h>

// Problem constants
#define BB   8
#define TT   2048
#define DIN  512
#define DD   1024
#define MTOT (BB*TT)        // 16384
#define LN_EPS 1e-5f

// Scratch (static __device__ arrays: no runtime allocation)
__device__ float g_a[(size_t)MTOT * DD];   // a_step
__device__ float g_b[(size_t)MTOT * DD];   // b_step
__device__ float g_h[(size_t)MTOT * DD];   // h_post

// ---------------------------------------------------------------------------
// Kernel 1: dual GEMM (x@Wd, x@Wb) + fused discretization epilogue.
// C tile per CTA: 128 (M) x 64 (N), for BOTH weight matrices (shares x tile).
// Per-thread micro-tile: 8x4 per matrix. 256 threads. K-step 16.
// ---------------------------------------------------------------------------
#define BM 128
#define BN 64
#define BK 16
#define KT (DIN / BK)   // 32

__global__ __launch_bounds__(256)
void gemm_epi_kernel(const float* __restrict__ x,
                     const float* __restrict__ Wd,
                     const float* __restrict__ bd,
                     const float* __restrict__ Wb,
                     const float* __restrict__ bb,
                     const float* __restrict__ A_log)
{
    __shared__ float As [BK][BM];   // x tile, transposed: As[k][m]
    __shared__ float Bds[BK][BN];   // Wd tile
    __shared__ float Bbs[BK][BN];   // Wb tile

    const int tid = threadIdx.x;
    const int m0  = blockIdx.y * BM;
    const int n0  = blockIdx.x * BN;

    // loader mapping
    const int a_m  = tid >> 2;       // 0..63 (plus +64 second half)
    const int a_kq = (tid & 3) * 4;  // 0,4,8,12
    const int w_k  = tid >> 4;       // 0..15
    const int w_n  = (tid & 15) * 4; // 0..60

    // compute mapping
    const int tm = (tid >> 4) * 8;   // row offset in tile
    const int tn = (tid & 15) * 4;   // col offset in tile

    float cd[8][4], cb[8][4];
    #pragma unroll
    for (int i = 0; i < 8; i++)
        #pragma unroll
        for (int j = 0; j < 4; j++) { cd[i][j] = 0.f; cb[i][j] = 0.f; }

    const float* xg0 = x  + (size_t)(m0 + a_m)      * DIN + a_kq;
    const float* xg1 = x  + (size_t)(m0 + a_m + 64) * DIN + a_kq;
    const float* wdg = Wd + (size_t)w_k * DD + n0 + w_n;
    const float* wbg = Wb + (size_t)w_k * DD + n0 + w_n;

    // initial stage into registers
    float4 xa0 = *(const float4*)xg0;
    float4 xa1 = *(const float4*)xg1;
    float4 wdv = *(const float4*)wdg;
    float4 wbv = *(const float4*)wbg;

    for (int kt = 0; kt < KT; ++kt) {
        // regs -> smem
        As[a_kq + 0][a_m] = xa0.x; As[a_kq + 1][a_m] = xa0.y;
        As[a_kq + 2][a_m] = xa0.z; As[a_kq + 3][a_m] = xa0.w;
        As[a_kq + 0][a_m + 64] = xa1.x; As[a_kq + 1][a_m + 64] = xa1.y;
        As[a_kq + 2][a_m + 64] = xa1.z; As[a_kq + 3][a_m + 64] = xa1.w;
        *(float4*)&Bds[w_k][w_n] = wdv;
        *(float4*)&Bbs[w_k][w_n] = wbv;
        __syncthreads();

        // prefetch next K-tile while computing this one
        if (kt + 1 < KT) {
            const int ko = (kt + 1) * BK;
            xa0 = *(const float4*)(xg0 + ko);
            xa1 = *(const float4*)(xg1 + ko);
            wdv = *(const float4*)(wdg + (size_t)ko * DD);
            wbv = *(const float4*)(wbg + (size_t)ko * DD);
        }

        #pragma unroll
        for (int kk = 0; kk < BK; ++kk) {
            float4 af0 = *(const float4*)&As[kk][tm];
            float4 af1 = *(const float4*)&As[kk][tm + 4];
            float4 d4  = *(const float4*)&Bds[kk][tn];
            float4 b4  = *(const float4*)&Bbs[kk][tn];
            float af[8] = {af0.x, af0.y, af0.z, af0.w, af1.x, af1.y, af1.z, af1.w};
            float dl[4] = {d4.x, d4.y, d4.z, d4.w};
            float bl[4] = {b4.x, b4.y, b4.z, b4.w};
            #pragma unroll
            for (int i = 0; i < 8; i++) {
                #pragma unroll
                for (int j = 0; j < 4; j++) {
                    cd[i][j] = fmaf(af[i], dl[j], cd[i][j]);
                    cb[i][j] = fmaf(af[i], bl[j], cb[i][j]);
                }
            }
        }
        __syncthreads();
    }

    // Epilogue: delta = softplus(yd + bd); b_step = delta*(yb + bb);
    //           a_step = exp(-delta * exp(A_log))
    const int n = n0 + tn;
    float4 bd4 = *(const float4*)&bd[n];
    float4 bb4 = *(const float4*)&bb[n];
    float4 al4 = *(const float4*)&A_log[n];
    float Av[4] = {expf(al4.x), expf(al4.y), expf(al4.z), expf(al4.w)};
    float bdv4[4] = {bd4.x, bd4.y, bd4.z, bd4.w};
    float bbv4[4] = {bb4.x, bb4.y, bb4.z, bb4.w};

    #pragma unroll
    for (int i = 0; i < 8; i++) {
        const int m = m0 + tm + i;
        float4 av, bv;
        float ao[4], bo[4];
        #pragma unroll
        for (int j = 0; j < 4; j++) {
            float zd = cd[i][j] + bdv4[j];
            // stable softplus: max(z,0) + log1p(exp(-|z|))
            float sp = fmaxf(zd, 0.f) + log1pf(expf(-fabsf(zd)));
            bo[j] = sp * (cb[i][j] + bbv4[j]);
            ao[j] = expf(-sp * Av[j]);
        }
        av.x = ao[0]; av.y = ao[1]; av.z = ao[2]; av.w = ao[3];
        bv.x = bo[0]; bv.y = bo[1]; bv.z = bo[2]; bv.w = bo[3];
        *(float4*)&g_a[(size_t)m * DD + n] = av;
        *(float4*)&g_b[(size_t)m * DD + n] = bv;
    }
}

// ---------------------------------------------------------------------------
// Kernel 2: sequential spiking scan. One thread per (b, d) lane, T sequential.
// Unroll by 16 for memory-level parallelism (loads are h-independent).
// ---------------------------------------------------------------------------
#define SU 16

__global__ __launch_bounds__(256)
void scan_kernel(const float* __restrict__ thr, float* __restrict__ spikes)
{
    const int gid = blockIdx.x * blockDim.x + threadIdx.x;  // 0..8191
    const int b = gid >> 10;
    const int d = gid & (DD - 1);
    const size_t base = (size_t)b * TT * DD + d;

    const float* ap = g_a + base;
    const float* bp = g_b + base;
    float* hp = g_h + base;
    float* sp = spikes + base;

    const float th = thr[d];
    float h = 0.f;

    for (int t = 0; t < TT; t += SU) {
        float av[SU], bv[SU];
        #pragma unroll
        for (int j = 0; j < SU; j++) av[j] = ap[(size_t)(t + j) * DD];
        #pragma unroll
        for (int j = 0; j < SU; j++) bv[j] = bp[(size_t)(t + j) * DD];

        float hv[SU], sv[SU];
        #pragma unroll
        for (int j = 0; j < SU; j++) {
            h = fmaf(av[j], h, bv[j]);
            float s = (h - th > 0.f) ? 1.f : 0.f;
            if (s > 0.f) h = 0.f;   // h * (1 - s)
            hv[j] = h; sv[j] = s;
        }
        #pragma unroll
        for (int j = 0; j < SU; j++) hp[(size_t)(t + j) * DD] = hv[j];
        #pragma unroll
        for (int j = 0; j < SU; j++) sp[(size_t)(t + j) * DD] = sv[j];
    }
}

// ---------------------------------------------------------------------------
// Kernel 3: LayerNorm over D=1024, one CTA (256 threads x float4) per row.
// Two-pass (mean, then centered variance) for accuracy.
// ---------------------------------------------------------------------------
__global__ __launch_bounds__(256)
void ln_kernel(const float* __restrict__ gamma, const float* __restrict__ beta,
               float* __restrict__ out)
{
    const int row = blockIdx.x;
    const int tid = threadIdx.x;
    const int lane = tid & 31, wid = tid >> 5;
    const float* hrow = g_h + (size_t)row * DD;

    __shared__ float red[8];

    float4 v = *(const float4*)&hrow[tid * 4];
    float s = v.x + v.y + v.z + v.w;
    #pragma unroll
    for (int o = 16; o > 0; o >>= 1) s += __shfl_xor_sync(0xffffffffu, s, o);
    if (lane == 0) red[wid] = s;
    __syncthreads();
    float tot = 0.f;
    #pragma unroll
    for (int i = 0; i < 8; i++) tot += red[i];
    const float mu = tot * (1.0f / (float)DD);

    float dx0 = v.x - mu, dx1 = v.y - mu, dx2 = v.z - mu, dx3 = v.w - mu;
    float ss = dx0 * dx0 + dx1 * dx1 + dx2 * dx2 + dx3 * dx3;
    __syncthreads();   // protect red[] reuse
    #pragma unroll
    for (int o = 16; o > 0; o >>= 1) ss += __shfl_xor_sync(0xffffffffu, ss, o);
    if (lane == 0) red[wid] = ss;
    __syncthreads();
    float tot2 = 0.f;
    #pragma unroll
    for (int i = 0; i < 8; i++) tot2 += red[i];
    const float rstd = rsqrtf(tot2 * (1.0f / (float)DD) + LN_EPS);

    float4 g = *(const float4*)&gamma[tid * 4];
    float4 bt = *(const float4*)&beta[tid * 4];
    float4 o4;
    o4.x = dx0 * rstd * g.x + bt.x;
    o4.y = dx1 * rstd * g.y + bt.y;
    o4.z = dx2 * rstd * g.z + bt.z;
    o4.w = dx3 * rstd * g.w + bt.w;
    *(float4*)&out[(size_t)row * DD + tid * 4] = o4;
}

// ---------------------------------------------------------------------------
extern "C" void kernel_launch(void* const* d_in, const int* in_sizes, int n_in,
                              void* d_out, int out_size)
{
    const float* x     = (const float*)d_in[0];
    const float* Wd    = (const float*)d_in[1];
    const float* bd    = (const float*)d_in[2];
    const float* Wb    = (const float*)d_in[3];
    const float* bb    = (const float*)d_in[4];
    const float* A_log = (const float*)d_in[5];
    const float* thr   = (const float*)d_in[6];
    const float* gamma = (const float*)d_in[7];
    const float* beta  = (const float*)d_in[8];

    float* out    = (float*)d_out;
    float* spikes = out + (size_t)MTOT * DD;   // tuple (out, spikes) concatenated

    dim3 ggrid(DD / BN, MTOT / BM);            // (16, 128) = 2048 CTAs
    gemm_epi_kernel<<<ggrid, 256>>>(x, Wd, bd, Wb, bb, A_log);

    scan_kernel<<<(BB * DD) / 256, 256>>>(thr, spikes);   // 32 CTAs

    ln_kernel<<<MTOT, 256>>>(gamma, beta, out);           // 16384 CTAs
}

// round 5
// speedup vs baseline: 1.0801x; 1.0801x over previous
#include <cuda_runtime.h>
#include <math.h>

// Problem constants
#define BB   8
#define TT   2048
#define DIN  512
#define DD   1024
#define MTOT (BB*TT)        // 16384
#define LN_EPS 1e-5f

// Scratch (static __device__ arrays: no runtime allocation)
__device__ float g_a[(size_t)MTOT * DD];   // a_step
__device__ float g_b[(size_t)MTOT * DD];   // b_step
__device__ float g_h[(size_t)MTOT * DD];   // h_post

// ---------------------------------------------------------------------------
// Kernel 1: dual GEMM (x@Wd, x@Wb) + fused discretization epilogue.
// CRITICAL: each output is ONE sequential-k fp32 FMA chain (k = 0..511 in
// order) — this bit-matches the cuBLAS fp32 SGEMM the reference uses, which
// keeps the chaotic spike threshold decisions identical. Do NOT reorder.
// C tile per CTA: 128 (M) x 64 (N) for BOTH weight matrices (shared x tile).
// Per-thread micro-tile: 8x4 per matrix. 256 threads. BK=16, double-buffered.
// ---------------------------------------------------------------------------
#define BM 128
#define BN 64
#define BK 16
#define KT (DIN / BK)   // 32

__global__ __launch_bounds__(256, 2)
void gemm_epi_kernel(const float* __restrict__ x,
                     const float* __restrict__ Wd,
                     const float* __restrict__ bd,
                     const float* __restrict__ Wb,
                     const float* __restrict__ bb,
                     const float* __restrict__ A_log)
{
    __shared__ float As [2][BK][BM];   // x tile, transposed: As[k][m]
    __shared__ float Bds[2][BK][BN];   // Wd tile
    __shared__ float Bbs[2][BK][BN];   // Wb tile

    const int tid = threadIdx.x;
    const int m0  = blockIdx.y * BM;
    const int n0  = blockIdx.x * BN;

    // loader mapping
    const int a_m  = tid >> 2;       // 0..63 (plus +64 second half)
    const int a_kq = (tid & 3) * 4;  // 0,4,8,12
    const int w_k  = tid >> 4;       // 0..15
    const int w_n  = (tid & 15) * 4; // 0..60

    // compute mapping
    const int tm = (tid >> 4) * 8;   // row offset in tile
    const int tn = (tid & 15) * 4;   // col offset in tile

    float cd[8][4], cb[8][4];
    #pragma unroll
    for (int i = 0; i < 8; i++)
        #pragma unroll
        for (int j = 0; j < 4; j++) { cd[i][j] = 0.f; cb[i][j] = 0.f; }

    const float* xg0 = x  + (size_t)(m0 + a_m)      * DIN + a_kq;
    const float* xg1 = x  + (size_t)(m0 + a_m + 64) * DIN + a_kq;
    const float* wdg = Wd + (size_t)w_k * DD + n0 + w_n;
    const float* wbg = Wb + (size_t)w_k * DD + n0 + w_n;

    // stage k-tile 0 into buffer 0
    {
        float4 xa0 = *(const float4*)xg0;
        float4 xa1 = *(const float4*)xg1;
        float4 wdv = *(const float4*)wdg;
        float4 wbv = *(const float4*)wbg;
        As[0][a_kq + 0][a_m] = xa0.x; As[0][a_kq + 1][a_m] = xa0.y;
        As[0][a_kq + 2][a_m] = xa0.z; As[0][a_kq + 3][a_m] = xa0.w;
        As[0][a_kq + 0][a_m + 64] = xa1.x; As[0][a_kq + 1][a_m + 64] = xa1.y;
        As[0][a_kq + 2][a_m + 64] = xa1.z; As[0][a_kq + 3][a_m + 64] = xa1.w;
        *(float4*)&Bds[0][w_k][w_n] = wdv;
        *(float4*)&Bbs[0][w_k][w_n] = wbv;
    }
    __syncthreads();

    for (int kt = 0; kt < KT; ++kt) {
        const int buf = kt & 1;

        // prefetch next K-tile from global while computing this one
        float4 xa0, xa1, wdv, wbv;
        if (kt + 1 < KT) {
            const int ko = (kt + 1) * BK;
            xa0 = *(const float4*)(xg0 + ko);
            xa1 = *(const float4*)(xg1 + ko);
            wdv = *(const float4*)(wdg + (size_t)ko * DD);
            wbv = *(const float4*)(wbg + (size_t)ko * DD);
        }

        #pragma unroll
        for (int kk = 0; kk < BK; ++kk) {
            float4 af0 = *(const float4*)&As[buf][kk][tm];
            float4 af1 = *(const float4*)&As[buf][kk][tm + 4];
            float4 d4  = *(const float4*)&Bds[buf][kk][tn];
            float4 b4  = *(const float4*)&Bbs[buf][kk][tn];
            float af[8] = {af0.x, af0.y, af0.z, af0.w, af1.x, af1.y, af1.z, af1.w};
            float dl[4] = {d4.x, d4.y, d4.z, d4.w};
            float bl[4] = {b4.x, b4.y, b4.z, b4.w};
            #pragma unroll
            for (int i = 0; i < 8; i++) {
                #pragma unroll
                for (int j = 0; j < 4; j++) {
                    cd[i][j] = fmaf(af[i], dl[j], cd[i][j]);
                    cb[i][j] = fmaf(af[i], bl[j], cb[i][j]);
                }
            }
        }

        // stage next tile into the other buffer; one sync per k-tile
        if (kt + 1 < KT) {
            const int nb = buf ^ 1;
            As[nb][a_kq + 0][a_m] = xa0.x; As[nb][a_kq + 1][a_m] = xa0.y;
            As[nb][a_kq + 2][a_m] = xa0.z; As[nb][a_kq + 3][a_m] = xa0.w;
            As[nb][a_kq + 0][a_m + 64] = xa1.x; As[nb][a_kq + 1][a_m + 64] = xa1.y;
            As[nb][a_kq + 2][a_m + 64] = xa1.z; As[nb][a_kq + 3][a_m + 64] = xa1.w;
            *(float4*)&Bds[nb][w_k][w_n] = wdv;
            *(float4*)&Bbs[nb][w_k][w_n] = wbv;
            __syncthreads();
        }
    }

    // Epilogue: delta = softplus(yd + bd); b_step = delta*(yb + bb);
    //           a_step = exp(-delta * exp(A_log))   (identical to round 1)
    const int n = n0 + tn;
    float4 bd4 = *(const float4*)&bd[n];
    float4 bb4 = *(const float4*)&bb[n];
    float4 al4 = *(const float4*)&A_log[n];
    float Av[4] = {expf(al4.x), expf(al4.y), expf(al4.z), expf(al4.w)};
    float bdv4[4] = {bd4.x, bd4.y, bd4.z, bd4.w};
    float bbv4[4] = {bb4.x, bb4.y, bb4.z, bb4.w};

    #pragma unroll
    for (int i = 0; i < 8; i++) {
        const int m = m0 + tm + i;
        float4 av, bv;
        float ao[4], bo[4];
        #pragma unroll
        for (int j = 0; j < 4; j++) {
            float zd = cd[i][j] + bdv4[j];
            float sp = fmaxf(zd, 0.f) + log1pf(expf(-fabsf(zd)));
            bo[j] = sp * (cb[i][j] + bbv4[j]);
            ao[j] = expf(-sp * Av[j]);
        }
        av.x = ao[0]; av.y = ao[1]; av.z = ao[2]; av.w = ao[3];
        bv.x = bo[0]; bv.y = bo[1]; bv.z = bo[2]; bv.w = bo[3];
        *(float4*)&g_a[(size_t)m * DD + n] = av;
        *(float4*)&g_b[(size_t)m * DD + n] = bv;
    }
}

// ---------------------------------------------------------------------------
// Kernel 2: sequential spiking scan. 8192 lanes, 128 blocks x 64 threads
// (spreads over ~128 SMs). Unroll 32, front-batched loads for deep MLP.
// fmaf chain identical to round 1 (bit-exact spikes).
// ---------------------------------------------------------------------------
#define SU 32

__global__ __launch_bounds__(64)
void scan_kernel(const float* __restrict__ thr, float* __restrict__ spikes)
{
    const int gid = blockIdx.x * 64 + threadIdx.x;   // 0..8191
    const int b = gid >> 10;
    const int d = gid & (DD - 1);
    const size_t base = (size_t)b * TT * DD + d;

    const float* ap = g_a + base;
    const float* bp = g_b + base;
    float* hp = g_h + base;
    float* sp = spikes + base;

    const float th = thr[d];
    float h = 0.f;

    for (int t = 0; t < TT; t += SU) {
        float av[SU], bv[SU];
        #pragma unroll
        for (int j = 0; j < SU; j++) av[j] = ap[(size_t)(t + j) * DD];
        #pragma unroll
        for (int j = 0; j < SU; j++) bv[j] = bp[(size_t)(t + j) * DD];

        #pragma unroll
        for (int j = 0; j < SU; j++) {
            h = fmaf(av[j], h, bv[j]);
            float s = (h - th > 0.f) ? 1.f : 0.f;
            if (s > 0.f) h = 0.f;
            hp[(size_t)(t + j) * DD] = h;
            sp[(size_t)(t + j) * DD] = s;
        }
    }
}

// ---------------------------------------------------------------------------
// Kernel 3: LayerNorm over D=1024, one CTA (256 threads x float4) per row.
// ---------------------------------------------------------------------------
__global__ __launch_bounds__(256)
void ln_kernel(const float* __restrict__ gamma, const float* __restrict__ beta,
               float* __restrict__ out)
{
    const int row = blockIdx.x;
    const int tid = threadIdx.x;
    const int lane = tid & 31, wid = tid >> 5;
    const float* hrow = g_h + (size_t)row * DD;

    __shared__ float red[8];

    float4 v = *(const float4*)&hrow[tid * 4];
    float s = v.x + v.y + v.z + v.w;
    #pragma unroll
    for (int o = 16; o > 0; o >>= 1) s += __shfl_xor_sync(0xffffffffu, s, o);
    if (lane == 0) red[wid] = s;
    __syncthreads();
    float tot = 0.f;
    #pragma unroll
    for (int i = 0; i < 8; i++) tot += red[i];
    const float mu = tot * (1.0f / (float)DD);

    float dx0 = v.x - mu, dx1 = v.y - mu, dx2 = v.z - mu, dx3 = v.w - mu;
    float ss = dx0 * dx0 + dx1 * dx1 + dx2 * dx2 + dx3 * dx3;
    __syncthreads();   // protect red[] reuse
    #pragma unroll
    for (int o = 16; o > 0; o >>= 1) ss += __shfl_xor_sync(0xffffffffu, ss, o);
    if (lane == 0) red[wid] = ss;
    __syncthreads();
    float tot2 = 0.f;
    #pragma unroll
    for (int i = 0; i < 8; i++) tot2 += red[i];
    const float rstd = rsqrtf(tot2 * (1.0f / (float)DD) + LN_EPS);

    float4 g = *(const float4*)&gamma[tid * 4];
    float4 bt = *(const float4*)&beta[tid * 4];
    float4 o4;
    o4.x = dx0 * rstd * g.x + bt.x;
    o4.y = dx1 * rstd * g.y + bt.y;
    o4.z = dx2 * rstd * g.z + bt.z;
    o4.w = dx3 * rstd * g.w + bt.w;
    *(float4*)&out[(size_t)row * DD + tid * 4] = o4;
}

// ---------------------------------------------------------------------------
extern "C" void kernel_launch(void* const* d_in, const int* in_sizes, int n_in,
                              void* d_out, int out_size)
{
    const float* x     = (const float*)d_in[0];
    const float* Wd    = (const float*)d_in[1];
    const float* bd    = (const float*)d_in[2];
    const float* Wb    = (const float*)d_in[3];
    const float* bb    = (const float*)d_in[4];
    const float* A_log = (const float*)d_in[5];
    const float* thr   = (const float*)d_in[6];
    const float* gamma = (const float*)d_in[7];
    const float* beta  = (const float*)d_in[8];

    float* out    = (float*)d_out;
    float* spikes = out + (size_t)MTOT * DD;   // tuple (out, spikes) concatenated

    dim3 ggrid(DD / BN, MTOT / BM);            // (16, 128) = 2048 CTAs
    gemm_epi_kernel<<<ggrid, 256>>>(x, Wd, bd, Wb, bb, A_log);

    scan_kernel<<<(BB * DD) / 64, 64>>>(thr, spikes);   // 128 CTAs x 64

    ln_kernel<<<MTOT, 256>>>(gamma, beta, out);         // 16384 CTAs
}

// round 6
// speedup vs baseline: 1.1493x; 1.0641x over previous
#include <cuda_runtime.h>
#include <math.h>

// Problem constants
#define BB   8
#define TT   2048
#define DIN  512
#define DD   1024
#define MTOT (BB*TT)        // 16384
#define LN_EPS 1e-5f

typedef unsigned long long ull;

// Scratch (static __device__ arrays: no runtime allocation)
__device__ float g_ab[(size_t)MTOT * DD * 2];  // interleaved (a,b) pairs
__device__ float g_h[(size_t)MTOT * DD];       // h_post

// ---------------------------------------------------------------------------
// Packed f32x2 helpers. Each lane is an independent IEEE fp32 rn FMA, so the
// per-element accumulation chain is bit-identical to scalar fmaf.
// ---------------------------------------------------------------------------
__device__ __forceinline__ ull pk2(float lo, float hi) {
    ull r; asm("mov.b64 %0, {%1, %2};" : "=l"(r) : "f"(lo), "f"(hi)); return r;
}
__device__ __forceinline__ float2 up2(ull v) {
    float2 f; asm("mov.b64 {%0, %1}, %2;" : "=f"(f.x), "=f"(f.y) : "l"(v)); return f;
}
__device__ __forceinline__ ull fma2(ull a, ull b, ull c) {
#if defined(__CUDA_ARCH__) && (__CUDA_ARCH__ >= 1000)
    ull d;
    asm("fma.rn.f32x2 %0, %1, %2, %3;" : "=l"(d) : "l"(a), "l"(b), "l"(c));
    return d;
#else
    float2 af = up2(a), bf = up2(b), cf = up2(c);
    return pk2(fmaf(af.x, bf.x, cf.x), fmaf(af.y, bf.y, cf.y));
#endif
}

// ---------------------------------------------------------------------------
// Kernel 1: dual GEMM (x@Wd, x@Wb) + fused discretization epilogue.
// CRITICAL: each output element is ONE sequential-k fp32 FMA chain
// (k = 0..511 in order) — bit-matches the reference SGEMM so the chaotic
// spike threshold decisions stay identical. FFMA2 lanes are independent,
// chain order unchanged. Do NOT reorder.
// CTA tile 128x64 for BOTH matrices; per-thread 8x4 per matrix via f32x2.
// ---------------------------------------------------------------------------
#define BM 128
#define BN 64
#define BK 16
#define KT (DIN / BK)   // 32

__global__ __launch_bounds__(256, 2)
void gemm_epi_kernel(const float* __restrict__ x,
                     const float* __restrict__ Wd,
                     const float* __restrict__ bd,
                     const float* __restrict__ Wb,
                     const float* __restrict__ bb,
                     const float* __restrict__ A_log)
{
    __shared__ float As [2][BK][BM];   // x tile, transposed: As[k][m]
    __shared__ float Bds[2][BK][BN];   // Wd tile
    __shared__ float Bbs[2][BK][BN];   // Wb tile

    const int tid = threadIdx.x;
    const int m0  = blockIdx.y * BM;
    const int n0  = blockIdx.x * BN;

    // loader mapping
    const int a_m  = tid >> 2;       // 0..63 (plus +64 second half)
    const int a_kq = (tid & 3) * 4;  // 0,4,8,12
    const int w_k  = tid >> 4;       // 0..15
    const int w_n  = (tid & 15) * 4; // 0..60

    // compute mapping
    const int tm = (tid >> 4) * 8;   // row offset in tile
    const int tn = (tid & 15) * 4;   // col offset in tile

    // packed accumulators: [i][jp], jp pairs (j0,j1) and (j2,j3)
    ull cdp[8][2], cbp[8][2];
    #pragma unroll
    for (int i = 0; i < 8; i++) {
        cdp[i][0] = 0ull; cdp[i][1] = 0ull;
        cbp[i][0] = 0ull; cbp[i][1] = 0ull;
    }

    const float* xg0 = x  + (size_t)(m0 + a_m)      * DIN + a_kq;
    const float* xg1 = x  + (size_t)(m0 + a_m + 64) * DIN + a_kq;
    const float* wdg = Wd + (size_t)w_k * DD + n0 + w_n;
    const float* wbg = Wb + (size_t)w_k * DD + n0 + w_n;

    // stage k-tile 0 into buffer 0
    {
        float4 xa0 = *(const float4*)xg0;
        float4 xa1 = *(const float4*)xg1;
        float4 wdv = *(const float4*)wdg;
        float4 wbv = *(const float4*)wbg;
        As[0][a_kq + 0][a_m] = xa0.x; As[0][a_kq + 1][a_m] = xa0.y;
        As[0][a_kq + 2][a_m] = xa0.z; As[0][a_kq + 3][a_m] = xa0.w;
        As[0][a_kq + 0][a_m + 64] = xa1.x; As[0][a_kq + 1][a_m + 64] = xa1.y;
        As[0][a_kq + 2][a_m + 64] = xa1.z; As[0][a_kq + 3][a_m + 64] = xa1.w;
        *(float4*)&Bds[0][w_k][w_n] = wdv;
        *(float4*)&Bbs[0][w_k][w_n] = wbv;
    }
    __syncthreads();

    for (int kt = 0; kt < KT; ++kt) {
        const int buf = kt & 1;

        // prefetch next K-tile from global while computing this one
        float4 xa0, xa1, wdv, wbv;
        if (kt + 1 < KT) {
            const int ko = (kt + 1) * BK;
            xa0 = *(const float4*)(xg0 + ko);
            xa1 = *(const float4*)(xg1 + ko);
            wdv = *(const float4*)(wdg + (size_t)ko * DD);
            wbv = *(const float4*)(wbg + (size_t)ko * DD);
        }

        #pragma unroll
        for (int kk = 0; kk < BK; ++kk) {
            float4 af0 = *(const float4*)&As[buf][kk][tm];
            float4 af1 = *(const float4*)&As[buf][kk][tm + 4];
            // packed (j0,j1) and (j2,j3) weight pairs — 16B-aligned
            ulonglong2 dp = *(const ulonglong2*)&Bds[buf][kk][tn];
            ulonglong2 bp = *(const ulonglong2*)&Bbs[buf][kk][tn];
            float af[8] = {af0.x, af0.y, af0.z, af0.w, af1.x, af1.y, af1.z, af1.w};
            #pragma unroll
            for (int i = 0; i < 8; i++) {
                ull aa = pk2(af[i], af[i]);
                cdp[i][0] = fma2(aa, dp.x, cdp[i][0]);
                cdp[i][1] = fma2(aa, dp.y, cdp[i][1]);
                cbp[i][0] = fma2(aa, bp.x, cbp[i][0]);
                cbp[i][1] = fma2(aa, bp.y, cbp[i][1]);
            }
        }

        // stage next tile into the other buffer; one sync per k-tile
        if (kt + 1 < KT) {
            const int nb = buf ^ 1;
            As[nb][a_kq + 0][a_m] = xa0.x; As[nb][a_kq + 1][a_m] = xa0.y;
            As[nb][a_kq + 2][a_m] = xa0.z; As[nb][a_kq + 3][a_m] = xa0.w;
            As[nb][a_kq + 0][a_m + 64] = xa1.x; As[nb][a_kq + 1][a_m + 64] = xa1.y;
            As[nb][a_kq + 2][a_m + 64] = xa1.z; As[nb][a_kq + 3][a_m + 64] = xa1.w;
            *(float4*)&Bds[nb][w_k][w_n] = wdv;
            *(float4*)&Bbs[nb][w_k][w_n] = wbv;
            __syncthreads();
        }
    }

    // Epilogue: delta = softplus(yd + bd); b_step = delta*(yb + bb);
    //           a_step = exp(-delta * exp(A_log)); store interleaved (a,b).
    const int n = n0 + tn;
    float4 bd4 = *(const float4*)&bd[n];
    float4 bb4 = *(const float4*)&bb[n];
    float4 al4 = *(const float4*)&A_log[n];
    float Av[4] = {expf(al4.x), expf(al4.y), expf(al4.z), expf(al4.w)};
    float bdv4[4] = {bd4.x, bd4.y, bd4.z, bd4.w};
    float bbv4[4] = {bb4.x, bb4.y, bb4.z, bb4.w};

    #pragma unroll
    for (int i = 0; i < 8; i++) {
        const int m = m0 + tm + i;
        float2 d01 = up2(cdp[i][0]), d23 = up2(cdp[i][1]);
        float2 b01 = up2(cbp[i][0]), b23 = up2(cbp[i][1]);
        float yd[4] = {d01.x, d01.y, d23.x, d23.y};
        float yb[4] = {b01.x, b01.y, b23.x, b23.y};
        float ao[4], bo[4];
        #pragma unroll
        for (int j = 0; j < 4; j++) {
            float zd = yd[j] + bdv4[j];
            float sp = fmaxf(zd, 0.f) + log1pf(expf(-fabsf(zd)));
            bo[j] = sp * (yb[j] + bbv4[j]);
            ao[j] = expf(-sp * Av[j]);
        }
        float4 p0, p1;
        p0.x = ao[0]; p0.y = bo[0]; p0.z = ao[1]; p0.w = bo[1];
        p1.x = ao[2]; p1.y = bo[2]; p1.z = ao[3]; p1.w = bo[3];
        float* dst = g_ab + (size_t)m * (2 * DD) + 2 * n;
        *(float4*)dst = p0;
        *(float4*)(dst + 4) = p1;
    }
}

// ---------------------------------------------------------------------------
// Kernel 2: sequential spiking scan. 8192 lanes, 128 blocks x 64 threads.
// Reads interleaved (a,b) via LDG.64. fmaf chain identical (bit-exact spikes).
// ---------------------------------------------------------------------------
#define SU 32

__global__ __launch_bounds__(64)
void scan_kernel(const float* __restrict__ thr, float* __restrict__ spikes)
{
    const int gid = blockIdx.x * 64 + threadIdx.x;   // 0..8191
    const int b = gid >> 10;
    const int d = gid & (DD - 1);

    const float2* abp = (const float2*)g_ab + (size_t)b * TT * DD + d;
    float* hp = g_h    + (size_t)b * TT * DD + d;
    float* sp = spikes + (size_t)b * TT * DD + d;

    const float th = thr[d];
    float h = 0.f;

    for (int t = 0; t < TT; t += SU) {
        float2 ab[SU];
        #pragma unroll
        for (int j = 0; j < SU; j++) ab[j] = abp[(size_t)(t + j) * DD];

        #pragma unroll
        for (int j = 0; j < SU; j++) {
            h = fmaf(ab[j].x, h, ab[j].y);
            float s = (h - th > 0.f) ? 1.f : 0.f;
            if (s > 0.f) h = 0.f;
            hp[(size_t)(t + j) * DD] = h;
            sp[(size_t)(t + j) * DD] = s;
        }
    }
}

// ---------------------------------------------------------------------------
// Kernel 3: LayerNorm over D=1024, one CTA (256 threads x float4) per row.
// ---------------------------------------------------------------------------
__global__ __launch_bounds__(256)
void ln_kernel(const float* __restrict__ gamma, const float* __restrict__ beta,
               float* __restrict__ out)
{
    const int row = blockIdx.x;
    const int tid = threadIdx.x;
    const int lane = tid & 31, wid = tid >> 5;
    const float* hrow = g_h + (size_t)row * DD;

    __shared__ float red[8];

    float4 v = *(const float4*)&hrow[tid * 4];
    float s = v.x + v.y + v.z + v.w;
    #pragma unroll
    for (int o = 16; o > 0; o >>= 1) s += __shfl_xor_sync(0xffffffffu, s, o);
    if (lane == 0) red[wid] = s;
    __syncthreads();
    float tot = 0.f;
    #pragma unroll
    for (int i = 0; i < 8; i++) tot += red[i];
    const float mu = tot * (1.0f / (float)DD);

    float dx0 = v.x - mu, dx1 = v.y - mu, dx2 = v.z - mu, dx3 = v.w - mu;
    float ss = dx0 * dx0 + dx1 * dx1 + dx2 * dx2 + dx3 * dx3;
    __syncthreads();   // protect red[] reuse
    #pragma unroll
    for (int o = 16; o > 0; o >>= 1) ss += __shfl_xor_sync(0xffffffffu, ss, o);
    if (lane == 0) red[wid] = ss;
    __syncthreads();
    float tot2 = 0.f;
    #pragma unroll
    for (int i = 0; i < 8; i++) tot2 += red[i];
    const float rstd = rsqrtf(tot2 * (1.0f / (float)DD) + LN_EPS);

    float4 g = *(const float4*)&gamma[tid * 4];
    float4 bt = *(const float4*)&beta[tid * 4];
    float4 o4;
    o4.x = dx0 * rstd * g.x + bt.x;
    o4.y = dx1 * rstd * g.y + bt.y;
    o4.z = dx2 * rstd * g.z + bt.z;
    o4.w = dx3 * rstd * g.w + bt.w;
    *(float4*)&out[(size_t)row * DD + tid * 4] = o4;
}

// ---------------------------------------------------------------------------
extern "C" void kernel_launch(void* const* d_in, const int* in_sizes, int n_in,
                              void* d_out, int out_size)
{
    const float* x     = (const float*)d_in[0];
    const float* Wd    = (const float*)d_in[1];
    const float* bd    = (const float*)d_in[2];
    const float* Wb    = (const float*)d_in[3];
    const float* bb    = (const float*)d_in[4];
    const float* A_log = (const float*)d_in[5];
    const float* thr   = (const float*)d_in[6];
    const float* gamma = (const float*)d_in[7];
    const float* beta  = (const float*)d_in[8];

    float* out    = (float*)d_out;
    float* spikes = out + (size_t)MTOT * DD;   // tuple (out, spikes) concatenated

    dim3 ggrid(DD / BN, MTOT / BM);            // (16, 128) = 2048 CTAs
    gemm_epi_kernel<<<ggrid, 256>>>(x, Wd, bd, Wb, bb, A_log);

    scan_kernel<<<(BB * DD) / 64, 64>>>(thr, spikes);   // 128 CTAs x 64

    ln_kernel<<<MTOT, 256>>>(gamma, beta, out);         // 16384 CTAs
}